// round 2
// baseline (speedup 1.0000x reference)
#include <cuda_runtime.h>
#include <cstdint>

#define T_TOK 2048
#define HDIM  1024
#define EDIM  64
#define NTOPK 8
#define IDIM  512
#define GSZ   128

#define NSLOTS (T_TOK * NTOPK)   // 16384

// ---------------- device scratch (static; no dynamic allocation) ----------------
__device__ int   g_count[EDIM];
__device__ int   g_offset[EDIM + 1];
__device__ int   g_fill[EDIM];
__device__ int   g_topk_idx[NSLOTS];
__device__ float g_topk_w[NSLOTS];
__device__ int   g_tok[NSLOTS];    // token id per slot (grouped by expert)
__device__ float g_tw[NSLOTS];     // combine weight per slot
__device__ float g_h[(size_t)NSLOTS * IDIM];  // 33.5 MB activation buffer

// ---------------- packed f32x2 helpers ----------------
__device__ __forceinline__ unsigned long long pack2(float a, float b) {
    unsigned long long r;
    asm("mov.b64 %0, {%1, %2};" : "=l"(r) : "f"(a), "f"(b));
    return r;
}
__device__ __forceinline__ void ffma2(unsigned long long& d,
                                      unsigned long long a, unsigned long long b) {
    asm("fma.rn.f32x2 %0, %1, %2, %0;" : "+l"(d) : "l"(a), "l"(b));
}
__device__ __forceinline__ float lo32(unsigned long long v) {
    return __uint_as_float((unsigned int)(v & 0xFFFFFFFFull));
}
__device__ __forceinline__ float hi32(unsigned long long v) {
    return __uint_as_float((unsigned int)(v >> 32));
}

__device__ __forceinline__ float silu_f(float v) {
    return v / (1.0f + __expf(-v));
}

// ---------------- kernel 0: zero counts ----------------
__global__ void init_kernel() {
    int i = threadIdx.x;
    if (i < EDIM) g_count[i] = 0;
}

// ---------------- kernel 1: routing (logits -> top8 -> softmax over top8) ------
__global__ __launch_bounds__(256) void route_kernel(const float* __restrict__ x,
                                                    const float* __restrict__ gw) {
    int t = blockIdx.x;
    __shared__ float xs[HDIM];
    __shared__ float part[256];
    __shared__ float logit[EDIM];
    int tid = threadIdx.x;

    for (int i = tid; i < HDIM; i += 256) xs[i] = x[t * HDIM + i];
    __syncthreads();

    int e = tid & 63;
    int q = tid >> 6;           // quarter 0..3
    const float* w  = gw + e * HDIM + q * 256;
    const float* xq = xs + q * 256;
    float s = 0.f;
#pragma unroll 8
    for (int i = 0; i < 256; i++) s += xq[i] * w[i];
    part[tid] = s;
    __syncthreads();
    if (tid < 64)
        logit[tid] = part[tid] + part[tid + 64] + part[tid + 128] + part[tid + 192];
    __syncthreads();

    if (tid == 0) {
        float lv[NTOPK];
        int   li[NTOPK];
        for (int k = 0; k < NTOPK; k++) {
            float best = -1e30f; int bi = 0;
            for (int i = 0; i < EDIM; i++) {
                float v = logit[i];
                if (v > best) { best = v; bi = i; }
            }
            lv[k] = best; li[k] = bi;
            logit[bi] = -1e30f;
        }
        // softmax over selected logits == renormalized top-k softmax probs
        float m = lv[0];
        float wv[NTOPK];
        float sum = 0.f;
        for (int k = 0; k < NTOPK; k++) { wv[k] = __expf(lv[k] - m); sum += wv[k]; }
        float inv = 1.f / sum;
        for (int k = 0; k < NTOPK; k++) {
            g_topk_idx[t * NTOPK + k] = li[k];
            g_topk_w[t * NTOPK + k]   = wv[k] * inv;
            atomicAdd(&g_count[li[k]], 1);
        }
    }
}

// ---------------- kernel 2: prefix sum over expert counts ----------------
__global__ void prefix_kernel() {
    if (threadIdx.x == 0) {
        int acc = 0;
        for (int e = 0; e < EDIM; e++) {
            g_offset[e] = acc;
            acc += g_count[e];
            g_fill[e] = 0;
        }
        g_offset[EDIM] = acc;
    }
}

// ---------------- kernel 3: scatter tokens into per-expert lists ----------------
__global__ void fill_kernel() {
    int i = blockIdx.x * blockDim.x + threadIdx.x;
    if (i >= NSLOTS) return;
    int e = g_topk_idx[i];
    int slot = atomicAdd(&g_fill[e], 1);
    int pos = g_offset[e] + slot;
    g_tok[pos] = i / NTOPK;
    g_tw[pos]  = g_topk_w[i];
}

// ---------------- GEMM1: h = silu(x_gathered @ dequant(W1_e)^T) * cw -----------
// out[t, i] = sum_h x[t,h] * deq1[h, e*512 + i]
// qweight1: (1024, 4096) int32 ; qzeros1: (8, 4096) ; scales1: (8, 32768)
__global__ __launch_bounds__(256) void gemm1_kernel(const float* __restrict__ x,
                                                    const int*   __restrict__ qw1,
                                                    const int*   __restrict__ qz1,
                                                    const float* __restrict__ sc1) {
    const int e    = blockIdx.z;
    const int base = g_offset[e];
    const int cnt  = g_offset[e + 1] - base;
    const int m0   = blockIdx.y * 64;
    if (m0 >= cnt) return;
    const int i0 = blockIdx.x * 64;

    __shared__ float Xs[32][64];
    __shared__ float Ws[32][64];
    __shared__ int   toks[64];
    __shared__ float tws[64];

    const int tid = threadIdx.x;
    if (tid < 64) {
        int m = m0 + tid;
        toks[tid] = (m < cnt) ? g_tok[base + m] : 0;
        tws[tid]  = (m < cnt) ? g_tw[base + m] : 0.f;
    }

    const int tn = tid & 15;
    const int tm = tid >> 4;
    unsigned long long acc[2][4];
#pragma unroll
    for (int a = 0; a < 2; a++)
#pragma unroll
        for (int b = 0; b < 4; b++) acc[a][b] = 0ull;

    const int kk = tid & 31;   // X fill: k lane
    const int mg = tid >> 5;   // X fill: m group (8 tokens each)
    const int wcol = tid & 7;  // W fill: packed int32 column (0..7)
    const int wk   = tid >> 3; // W fill: k row (0..31)
    const int colbase = (e * IDIM + i0) >> 3;
    const int shifts[8] = {0, 16, 4, 20, 8, 24, 12, 28};

    for (int k0 = 0; k0 < HDIM; k0 += 32) {
        __syncthreads();
        // X tile (gathered rows)
#pragma unroll
        for (int mm = 0; mm < 8; mm++) {
            int m = mg * 8 + mm;
            Xs[kk][m] = x[toks[m] * HDIM + k0 + kk];
        }
        // W tile: on-the-fly AWQ dequant
        {
            int krow = k0 + wk;
            int g = krow >> 7;  // group (krow / 128)
            unsigned int qv = (unsigned int)qw1[krow * 4096 + colbase + wcol];
            unsigned int zv = (unsigned int)qz1[g * 4096 + colbase + wcol];
            const float* sp = sc1 + g * 32768 + e * IDIM + i0 + wcol * 8;
#pragma unroll
            for (int j = 0; j < 8; j++) {
                int sh = shifts[j];
                float q = (float)((qv >> sh) & 0xF);
                float z = (float)((zv >> sh) & 0xF);
                Ws[wk][wcol * 8 + j] = (q - z) * sp[j];
            }
        }
        __syncthreads();
#pragma unroll
        for (int k = 0; k < 32; k++) {
            float4 xa = *(const float4*)&Xs[k][tm * 4];
            float4 wa = *(const float4*)&Ws[k][tn * 4];
            unsigned long long x01 = pack2(xa.x, xa.y);
            unsigned long long x23 = pack2(xa.z, xa.w);
            unsigned long long w0 = pack2(wa.x, wa.x);
            unsigned long long w1 = pack2(wa.y, wa.y);
            unsigned long long w2 = pack2(wa.z, wa.z);
            unsigned long long w3 = pack2(wa.w, wa.w);
            ffma2(acc[0][0], x01, w0); ffma2(acc[1][0], x23, w0);
            ffma2(acc[0][1], x01, w1); ffma2(acc[1][1], x23, w1);
            ffma2(acc[0][2], x01, w2); ffma2(acc[1][2], x23, w2);
            ffma2(acc[0][3], x01, w3); ffma2(acc[1][3], x23, w3);
        }
    }

    // epilogue: silu * combine_weight -> g_h
#pragma unroll
    for (int r = 0; r < 4; r++) {
        int m = tm * 4 + r;
        if (m0 + m < cnt) {
            float tw = tws[m];
            float vv[4];
#pragma unroll
            for (int b = 0; b < 4; b++) {
                unsigned long long a = acc[r >> 1][b];
                float v = (r & 1) ? hi32(a) : lo32(a);
                vv[b] = silu_f(v) * tw;
            }
            float4 o = make_float4(vv[0], vv[1], vv[2], vv[3]);
            *(float4*)&g_h[(size_t)(base + m0 + m) * IDIM + i0 + tn * 4] = o;
        }
    }
}

// ---------------- GEMM2: out[t] += h_slot @ dequant(W2_e)^T --------------------
// out[t, h] += sum_i g_h[slot, i] * deq2[i, e*1024 + h]
// qweight2: (512, 8192) int32 ; qzeros2: (4, 8192) ; scales2: (4, 65536)
__global__ __launch_bounds__(256) void gemm2_kernel(const int*   __restrict__ qw2,
                                                    const int*   __restrict__ qz2,
                                                    const float* __restrict__ sc2,
                                                    float* __restrict__ out) {
    const int e    = blockIdx.z;
    const int base = g_offset[e];
    const int cnt  = g_offset[e + 1] - base;
    const int m0   = blockIdx.y * 64;
    if (m0 >= cnt) return;
    const int h0 = blockIdx.x * 64;

    __shared__ float Xs[32][64];
    __shared__ float Ws[32][64];
    __shared__ int   toks[64];

    const int tid = threadIdx.x;
    if (tid < 64) {
        int m = m0 + tid;
        toks[tid] = (m < cnt) ? g_tok[base + m] : 0;
    }

    const int tn = tid & 15;
    const int tm = tid >> 4;
    unsigned long long acc[2][4];
#pragma unroll
    for (int a = 0; a < 2; a++)
#pragma unroll
        for (int b = 0; b < 4; b++) acc[a][b] = 0ull;

    const int kk = tid & 31;
    const int mg = tid >> 5;
    const int wcol = tid & 7;
    const int wk   = tid >> 3;
    const int colbase = (e * HDIM + h0) >> 3;
    const int shifts[8] = {0, 16, 4, 20, 8, 24, 12, 28};

    for (int k0 = 0; k0 < IDIM; k0 += 32) {
        __syncthreads();
#pragma unroll
        for (int mm = 0; mm < 8; mm++) {
            int m = mg * 8 + mm;
            float v = 0.f;
            if (m0 + m < cnt)
                v = g_h[(size_t)(base + m0 + m) * IDIM + k0 + kk];
            Xs[kk][m] = v;
        }
        {
            int krow = k0 + wk;
            int g = krow >> 7;
            unsigned int qv = (unsigned int)qw2[krow * 8192 + colbase + wcol];
            unsigned int zv = (unsigned int)qz2[g * 8192 + colbase + wcol];
            const float* sp = sc2 + g * 65536 + e * HDIM + h0 + wcol * 8;
#pragma unroll
            for (int j = 0; j < 8; j++) {
                int sh = shifts[j];
                float q = (float)((qv >> sh) & 0xF);
                float z = (float)((zv >> sh) & 0xF);
                Ws[wk][wcol * 8 + j] = (q - z) * sp[j];
            }
        }
        __syncthreads();
#pragma unroll
        for (int k = 0; k < 32; k++) {
            float4 xa = *(const float4*)&Xs[k][tm * 4];
            float4 wa = *(const float4*)&Ws[k][tn * 4];
            unsigned long long x01 = pack2(xa.x, xa.y);
            unsigned long long x23 = pack2(xa.z, xa.w);
            unsigned long long w0 = pack2(wa.x, wa.x);
            unsigned long long w1 = pack2(wa.y, wa.y);
            unsigned long long w2 = pack2(wa.z, wa.z);
            unsigned long long w3 = pack2(wa.w, wa.w);
            ffma2(acc[0][0], x01, w0); ffma2(acc[1][0], x23, w0);
            ffma2(acc[0][1], x01, w1); ffma2(acc[1][1], x23, w1);
            ffma2(acc[0][2], x01, w2); ffma2(acc[1][2], x23, w2);
            ffma2(acc[0][3], x01, w3); ffma2(acc[1][3], x23, w3);
        }
    }

    // epilogue: atomic scatter into out (zero-initialized via memset)
#pragma unroll
    for (int r = 0; r < 4; r++) {
        int m = tm * 4 + r;
        if (m0 + m < cnt) {
            int t = toks[m];
#pragma unroll
            for (int b = 0; b < 4; b++) {
                unsigned long long a = acc[r >> 1][b];
                float v = (r & 1) ? hi32(a) : lo32(a);
                atomicAdd(&out[t * HDIM + h0 + tn * 4 + b], v);
            }
        }
    }
}

// ---------------- launch ----------------
extern "C" void kernel_launch(void* const* d_in, const int* in_sizes, int n_in,
                              void* d_out, int out_size) {
    const float* x   = (const float*)d_in[0];
    const float* gw  = (const float*)d_in[1];
    const int*   qw1 = (const int*)d_in[2];
    const int*   qz1 = (const int*)d_in[3];
    const float* sc1 = (const float*)d_in[4];
    const int*   qw2 = (const int*)d_in[5];
    const int*   qz2 = (const int*)d_in[6];
    const float* sc2 = (const float*)d_in[7];
    float* out = (float*)d_out;

    init_kernel<<<1, 64>>>();
    route_kernel<<<T_TOK, 256>>>(x, gw);
    prefix_kernel<<<1, 1>>>();
    fill_kernel<<<(NSLOTS + 255) / 256, 256>>>();
    cudaMemsetAsync(out, 0, (size_t)out_size * sizeof(float), 0);
    gemm1_kernel<<<dim3(IDIM / 64, T_TOK / 64, EDIM), 256>>>(x, qw1, qz1, sc1);
    gemm2_kernel<<<dim3(HDIM / 64, T_TOK / 64, EDIM), 256>>>(qw2, qz2, sc2, out);
}

// round 3
// speedup vs baseline: 1.6042x; 1.6042x over previous
#include <cuda_runtime.h>
#include <cstdint>
#include <cstddef>

#define T_TOK 2048
#define HDIM  1024
#define EDIM  64
#define NTOPK 8
#define IDIM  512

#define NSLOTS (T_TOK * NTOPK)      // 16384
#define PADSLOTS (NSLOTS + 128)

#define BM 128
#define BN 64
#define BK 32
#define KSTR 130                     // padded smem row stride (floats)
#define BUFSZ (BK * KSTR)            // 4160 floats per buffer
#define SMEM_BYTES (4 * BUFSZ * 4)   // 2 bufs x (X + Wdup) = 66560 B

typedef unsigned long long u64;

// ---------------- device scratch ----------------
__device__ int   g_count[EDIM];
__device__ int   g_offset[EDIM + 1];
__device__ int   g_fill[EDIM];
__device__ int   g_topk_idx[NSLOTS];
__device__ float g_topk_w[NSLOTS];
__device__ int   g_tok[PADSLOTS];     // padding stays 0 (never written)
__device__ float g_tw[PADSLOTS];
__device__ float g_h[(size_t)PADSLOTS * IDIM];

// ---------------- f32x2 helpers ----------------
__device__ __forceinline__ u64 pack2(float a, float b) {
    u64 r; asm("mov.b64 %0, {%1, %2};" : "=l"(r) : "f"(a), "f"(b)); return r;
}
__device__ __forceinline__ void ffma2(u64& d, u64 a, u64 b) {
    asm("fma.rn.f32x2 %0, %1, %2, %0;" : "+l"(d) : "l"(a), "l"(b));
}
__device__ __forceinline__ float lo32(u64 v) { return __uint_as_float((unsigned)(v & 0xFFFFFFFFull)); }
__device__ __forceinline__ float hi32(u64 v) { return __uint_as_float((unsigned)(v >> 32)); }
__device__ __forceinline__ float silu_f(float v) { return v / (1.0f + __expf(-v)); }

// ---------------- routing kernels (unchanged, not bottleneck) ----------------
__global__ void init_kernel() {
    int i = threadIdx.x;
    if (i < EDIM) g_count[i] = 0;
}

__global__ __launch_bounds__(256) void route_kernel(const float* __restrict__ x,
                                                    const float* __restrict__ gw) {
    int t = blockIdx.x;
    __shared__ float xs[HDIM];
    __shared__ float part[256];
    __shared__ float logit[EDIM];
    int tid = threadIdx.x;
    for (int i = tid; i < HDIM; i += 256) xs[i] = x[t * HDIM + i];
    __syncthreads();
    int e = tid & 63, q = tid >> 6;
    const float* w  = gw + e * HDIM + q * 256;
    const float* xq = xs + q * 256;
    float s = 0.f;
#pragma unroll 8
    for (int i = 0; i < 256; i++) s += xq[i] * w[i];
    part[tid] = s;
    __syncthreads();
    if (tid < 64)
        logit[tid] = part[tid] + part[tid + 64] + part[tid + 128] + part[tid + 192];
    __syncthreads();
    if (tid == 0) {
        float lv[NTOPK]; int li[NTOPK];
        for (int k = 0; k < NTOPK; k++) {
            float best = -1e30f; int bi = 0;
            for (int i = 0; i < EDIM; i++) { float v = logit[i]; if (v > best) { best = v; bi = i; } }
            lv[k] = best; li[k] = bi; logit[bi] = -1e30f;
        }
        float m = lv[0], sum = 0.f, wv[NTOPK];
        for (int k = 0; k < NTOPK; k++) { wv[k] = __expf(lv[k] - m); sum += wv[k]; }
        float inv = 1.f / sum;
        for (int k = 0; k < NTOPK; k++) {
            g_topk_idx[t * NTOPK + k] = li[k];
            g_topk_w[t * NTOPK + k]   = wv[k] * inv;
            atomicAdd(&g_count[li[k]], 1);
        }
    }
}

__global__ void prefix_kernel() {
    if (threadIdx.x == 0) {
        int acc = 0;
        for (int e = 0; e < EDIM; e++) { g_offset[e] = acc; acc += g_count[e]; g_fill[e] = 0; }
        g_offset[EDIM] = acc;
    }
}

__global__ void fill_kernel() {
    int i = blockIdx.x * blockDim.x + threadIdx.x;
    if (i >= NSLOTS) return;
    int e = g_topk_idx[i];
    int slot = atomicAdd(&g_fill[e], 1);
    int pos = g_offset[e] + slot;
    g_tok[pos] = i / NTOPK;
    g_tw[pos]  = g_topk_w[i];
}

// ---------------- shared GEMM pieces ----------------
// AWQ dequant of one packed int32 -> 8 duplicated f32x2 pairs into Wd row
__device__ __forceinline__ void dequant_store(float* wrow_base, int wk, int wcol,
                                              unsigned qv, unsigned zv,
                                              float4 s0, float4 s1) {
    float ss[8] = {s0.x, s0.y, s0.z, s0.w, s1.x, s1.y, s1.z, s1.w};
    u64* dst = (u64*)(wrow_base + wk * KSTR + wcol * 16);
    const int sh[8] = {0, 16, 4, 20, 8, 24, 12, 28};
#pragma unroll
    for (int j = 0; j < 8; j++) {
        float q = (float)((qv >> sh[j]) & 0xF);
        float z = (float)((zv >> sh[j]) & 0xF);
        float v = (q - z) * ss[j];
        dst[j] = pack2(v, v);
    }
}

// inner product over one BK tile: x m-pairs (LDS.64) x pre-duplicated w (LDS.64)
__device__ __forceinline__ void mm_compute(const float* __restrict__ xb,
                                           const float* __restrict__ wb,
                                           u64 acc[4][4]) {
#pragma unroll
    for (int k = 0; k < BK; k++) {
        const u64* xp = (const u64*)(xb + k * KSTR);
        const u64* wp = (const u64*)(wb + k * KSTR);
        u64 x0 = xp[0], x1 = xp[1], x2 = xp[2], x3 = xp[3];
        u64 w0 = wp[0], w1 = wp[1], w2 = wp[2], w3 = wp[3];
        ffma2(acc[0][0], x0, w0); ffma2(acc[0][1], x0, w1);
        ffma2(acc[0][2], x0, w2); ffma2(acc[0][3], x0, w3);
        ffma2(acc[1][0], x1, w0); ffma2(acc[1][1], x1, w1);
        ffma2(acc[1][2], x1, w2); ffma2(acc[1][3], x1, w3);
        ffma2(acc[2][0], x2, w0); ffma2(acc[2][1], x2, w1);
        ffma2(acc[2][2], x2, w2); ffma2(acc[2][3], x2, w3);
        ffma2(acc[3][0], x3, w0); ffma2(acc[3][1], x3, w1);
        ffma2(acc[3][2], x3, w2); ffma2(acc[3][3], x3, w3);
    }
}

// ---------------- GEMM1: g_h = silu(gather(x) @ deqW1^T) * tw ----------------
__global__ __launch_bounds__(256, 2) void gemm1_kernel(const float* __restrict__ x,
                                                       const int*   __restrict__ qw1,
                                                       const int*   __restrict__ qz1,
                                                       const float* __restrict__ sc1) {
    const int e    = blockIdx.z;
    const int base = g_offset[e];
    const int cnt  = g_offset[e + 1] - base;
    const int m0   = blockIdx.y * BM;
    if (m0 >= cnt) return;
    const int i0 = blockIdx.x * BN;

    extern __shared__ float sm[];
    float* Xs = sm;                 // [2][BK][KSTR] (m-contiguous rows)
    float* Wd = sm + 2 * BUFSZ;     // [2][BK][KSTR] (n duplicated f32x2)

    const int tid = threadIdx.x;
    const int tx  = tid & 15;       // n group
    const int ty  = tid >> 4;       // m group

    // X loader: 4 float4 per thread per tile; idx -> (m, kq)
    const float* xrow[4];
    int xsoff[4];
#pragma unroll
    for (int it = 0; it < 4; it++) {
        int idx = it * 256 + tid;
        int m   = idx >> 3;
        int kq  = idx & 7;
        int tok = g_tok[base + m0 + m];          // padded region reads 0
        xrow[it]  = x + (size_t)tok * HDIM + kq * 4;
        xsoff[it] = kq * 4 * KSTR + m;
    }

    const int wk   = tid >> 3;
    const int wcol = tid & 7;
    const int qcol = ((e * IDIM + i0) >> 3) + wcol;
    const float* scbase = sc1 + e * IDIM + i0 + wcol * 8;

    float4 xv[4]; unsigned qv, zv; float4 s0v, s1v;

    auto fetch = [&](int k0) {
#pragma unroll
        for (int it = 0; it < 4; it++) xv[it] = *(const float4*)(xrow[it] + k0);
        int krow = k0 + wk;
        int g = krow >> 7;
        qv = (unsigned)qw1[krow * 4096 + qcol];
        zv = (unsigned)qz1[g * 4096 + qcol];
        const float* sp = scbase + g * 32768;
        s0v = *(const float4*)sp;
        s1v = *(const float4*)(sp + 4);
    };
    auto stage = [&](int buf) {
        float* xb = Xs + buf * BUFSZ;
#pragma unroll
        for (int it = 0; it < 4; it++) {
            xb[xsoff[it]           ] = xv[it].x;
            xb[xsoff[it] + KSTR    ] = xv[it].y;
            xb[xsoff[it] + 2 * KSTR] = xv[it].z;
            xb[xsoff[it] + 3 * KSTR] = xv[it].w;
        }
        dequant_store(Wd + buf * BUFSZ, wk, wcol, qv, zv, s0v, s1v);
    };

    u64 acc[4][4];
#pragma unroll
    for (int a = 0; a < 4; a++)
#pragma unroll
        for (int b = 0; b < 4; b++) acc[a][b] = 0ull;

    fetch(0); stage(0);
    const int NT = HDIM / BK;
#pragma unroll 1
    for (int t = 0; t < NT; t++) {
        __syncthreads();
        if (t + 1 < NT) fetch((t + 1) * BK);
        mm_compute(Xs + (t & 1) * BUFSZ + ty * 8,
                   Wd + (t & 1) * BUFSZ + tx * 8, acc);
        if (t + 1 < NT) stage((t + 1) & 1);
    }

    // epilogue: silu * tw -> g_h
#pragma unroll
    for (int mp = 0; mp < 4; mp++) {
#pragma unroll
        for (int half = 0; half < 2; half++) {
            int gm = m0 + ty * 8 + 2 * mp + half;
            if (gm < cnt) {
                float tw = g_tw[base + gm];
                float v0 = half ? hi32(acc[mp][0]) : lo32(acc[mp][0]);
                float v1 = half ? hi32(acc[mp][1]) : lo32(acc[mp][1]);
                float v2 = half ? hi32(acc[mp][2]) : lo32(acc[mp][2]);
                float v3 = half ? hi32(acc[mp][3]) : lo32(acc[mp][3]);
                float4 o = make_float4(silu_f(v0) * tw, silu_f(v1) * tw,
                                       silu_f(v2) * tw, silu_f(v3) * tw);
                *(float4*)&g_h[(size_t)(base + gm) * IDIM + i0 + tx * 4] = o;
            }
        }
    }
}

// ---------------- GEMM2: out += g_h @ deqW2^T (atomic scatter) ----------------
__global__ __launch_bounds__(256, 2) void gemm2_kernel(const int*   __restrict__ qw2,
                                                       const int*   __restrict__ qz2,
                                                       const float* __restrict__ sc2,
                                                       float* __restrict__ out) {
    const int e    = blockIdx.z;
    const int base = g_offset[e];
    const int cnt  = g_offset[e + 1] - base;
    const int m0   = blockIdx.y * BM;
    if (m0 >= cnt) return;
    const int h0 = blockIdx.x * BN;

    extern __shared__ float sm[];
    float* Xs = sm;
    float* Wd = sm + 2 * BUFSZ;

    const int tid = threadIdx.x;
    const int tx  = tid & 15;
    const int ty  = tid >> 4;

    const float* xrow[4];
    int xsoff[4];
#pragma unroll
    for (int it = 0; it < 4; it++) {
        int idx = it * 256 + tid;
        int m   = idx >> 3;
        int kq  = idx & 7;
        xrow[it]  = g_h + (size_t)(base + m0 + m) * IDIM + kq * 4;  // rows contiguous
        xsoff[it] = kq * 4 * KSTR + m;
    }

    const int wk   = tid >> 3;
    const int wcol = tid & 7;
    const int qcol = ((e * HDIM + h0) >> 3) + wcol;
    const float* scbase = sc2 + e * HDIM + h0 + wcol * 8;

    float4 xv[4]; unsigned qv, zv; float4 s0v, s1v;

    auto fetch = [&](int k0) {
#pragma unroll
        for (int it = 0; it < 4; it++) xv[it] = *(const float4*)(xrow[it] + k0);
        int krow = k0 + wk;
        int g = krow >> 7;
        qv = (unsigned)qw2[krow * 8192 + qcol];
        zv = (unsigned)qz2[g * 8192 + qcol];
        const float* sp = scbase + g * 65536;
        s0v = *(const float4*)sp;
        s1v = *(const float4*)(sp + 4);
    };
    auto stage = [&](int buf) {
        float* xb = Xs + buf * BUFSZ;
#pragma unroll
        for (int it = 0; it < 4; it++) {
            xb[xsoff[it]           ] = xv[it].x;
            xb[xsoff[it] + KSTR    ] = xv[it].y;
            xb[xsoff[it] + 2 * KSTR] = xv[it].z;
            xb[xsoff[it] + 3 * KSTR] = xv[it].w;
        }
        dequant_store(Wd + buf * BUFSZ, wk, wcol, qv, zv, s0v, s1v);
    };

    u64 acc[4][4];
#pragma unroll
    for (int a = 0; a < 4; a++)
#pragma unroll
        for (int b = 0; b < 4; b++) acc[a][b] = 0ull;

    fetch(0); stage(0);
    const int NT = IDIM / BK;
#pragma unroll 1
    for (int t = 0; t < NT; t++) {
        __syncthreads();
        if (t + 1 < NT) fetch((t + 1) * BK);
        mm_compute(Xs + (t & 1) * BUFSZ + ty * 8,
                   Wd + (t & 1) * BUFSZ + tx * 8, acc);
        if (t + 1 < NT) stage((t + 1) & 1);
    }

#pragma unroll
    for (int mp = 0; mp < 4; mp++) {
#pragma unroll
        for (int half = 0; half < 2; half++) {
            int gm = m0 + ty * 8 + 2 * mp + half;
            if (gm < cnt) {
                int tokt = g_tok[base + gm];
                float* op = out + (size_t)tokt * HDIM + h0 + tx * 4;
                float v0 = half ? hi32(acc[mp][0]) : lo32(acc[mp][0]);
                float v1 = half ? hi32(acc[mp][1]) : lo32(acc[mp][1]);
                float v2 = half ? hi32(acc[mp][2]) : lo32(acc[mp][2]);
                float v3 = half ? hi32(acc[mp][3]) : lo32(acc[mp][3]);
                atomicAdd(op + 0, v0);
                atomicAdd(op + 1, v1);
                atomicAdd(op + 2, v2);
                atomicAdd(op + 3, v3);
            }
        }
    }
}

// ---------------- launch ----------------
extern "C" void kernel_launch(void* const* d_in, const int* in_sizes, int n_in,
                              void* d_out, int out_size) {
    const float* x   = (const float*)d_in[0];
    const float* gw  = (const float*)d_in[1];
    const int*   qw1 = (const int*)d_in[2];
    const int*   qz1 = (const int*)d_in[3];
    const float* sc1 = (const float*)d_in[4];
    const int*   qw2 = (const int*)d_in[5];
    const int*   qz2 = (const int*)d_in[6];
    const float* sc2 = (const float*)d_in[7];
    float* out = (float*)d_out;

    cudaFuncSetAttribute(gemm1_kernel, cudaFuncAttributeMaxDynamicSharedMemorySize, SMEM_BYTES);
    cudaFuncSetAttribute(gemm2_kernel, cudaFuncAttributeMaxDynamicSharedMemorySize, SMEM_BYTES);

    init_kernel<<<1, 64>>>();
    route_kernel<<<T_TOK, 256>>>(x, gw);
    prefix_kernel<<<1, 1>>>();
    fill_kernel<<<(NSLOTS + 255) / 256, 256>>>();
    cudaMemsetAsync(out, 0, (size_t)out_size * sizeof(float), 0);
    gemm1_kernel<<<dim3(IDIM / BN, T_TOK / BM, EDIM), 256, SMEM_BYTES>>>(x, qw1, qz1, sc1);
    gemm2_kernel<<<dim3(HDIM / BN, T_TOK / BM, EDIM), 256, SMEM_BYTES>>>(qw2, qz2, sc2, out);
}

// round 5
// speedup vs baseline: 3.6688x; 2.2870x over previous
#include <cuda_runtime.h>
#include <cuda_bf16.h>
#include <cstdint>
#include <cstddef>

#define T_TOK 2048
#define HDIM  1024
#define EDIM  64
#define NTOPK 8
#define IDIM  512

#define NSLOTS (T_TOK * NTOPK)      // 16384
#define PADSLOTS (NSLOTS + 128)

#define BM 128
#define BN 64
#define KC 64
#define AST 72                       // A smem row stride (bf16)
#define BST 72                       // B smem row stride (bf16)

// smem byte offsets
#define OFF_TOKS 0                   // 128 ints
#define OFF_TWS  512                 // 128 floats
#define OFF_SC   1024                // up to 512 floats (2048 B)
#define OFF_AH   3072                // 128 x 72 bf16 = 18432
#define OFF_AL   21504               // 18432
#define OFF_B    39936               // 64 x 72 bf16 = 9216
#define SMEM_TOTAL 49152

typedef unsigned int u32;

// ---------------- device scratch ----------------
__device__ int   g_count[EDIM];
__device__ int   g_offset[EDIM + 1];
__device__ int   g_fill[EDIM];
__device__ int   g_topk_idx[NSLOTS];
__device__ float g_topk_w[NSLOTS];
__device__ int   g_tok[PADSLOTS];
__device__ float g_tw[PADSLOTS];
__device__ float g_h[(size_t)PADSLOTS * IDIM];

__device__ __forceinline__ float silu_f(float v) { return v / (1.0f + __expf(-v)); }

__device__ __forceinline__ u32 smem_u32(const void* p) {
    u32 a;
    asm("{ .reg .u64 t; cvta.to.shared.u64 t, %1; cvt.u32.u64 %0, t; }" : "=r"(a) : "l"(p));
    return a;
}

#define LDMX4(r0, r1, r2, r3, addr) \
    asm volatile("ldmatrix.sync.aligned.m8n8.x4.shared.b16 {%0,%1,%2,%3}, [%4];" \
                 : "=r"(r0), "=r"(r1), "=r"(r2), "=r"(r3) : "r"(addr))

#define LDMX4T(r0, r1, r2, r3, addr) \
    asm volatile("ldmatrix.sync.aligned.m8n8.x4.trans.shared.b16 {%0,%1,%2,%3}, [%4];" \
                 : "=r"(r0), "=r"(r1), "=r"(r2), "=r"(r3) : "r"(addr))

#define MMA16816(d, a0, a1, a2, a3, b0, b1) \
    asm volatile("mma.sync.aligned.m16n8k16.row.col.f32.bf16.bf16.f32 " \
                 "{%0,%1,%2,%3}, {%4,%5,%6,%7}, {%8,%9}, {%0,%1,%2,%3};" \
                 : "+f"((d)[0]), "+f"((d)[1]), "+f"((d)[2]), "+f"((d)[3]) \
                 : "r"(a0), "r"(a1), "r"(a2), "r"(a3), "r"(b0), "r"(b1))

// ---------------- routing kernels ----------------
__global__ void init_kernel() {
    int i = threadIdx.x;
    if (i < EDIM) g_count[i] = 0;
}

__global__ __launch_bounds__(256) void route_kernel(const float* __restrict__ x,
                                                    const float* __restrict__ gw) {
    int t = blockIdx.x;
    __shared__ float xs[HDIM];
    __shared__ float part[256];
    __shared__ float logit[EDIM];
    int tid = threadIdx.x;
    for (int i = tid; i < HDIM; i += 256) xs[i] = x[t * HDIM + i];
    __syncthreads();
    int e = tid & 63, q = tid >> 6;
    const float* w  = gw + e * HDIM + q * 256;
    const float* xq = xs + q * 256;
    float s = 0.f;
#pragma unroll 8
    for (int i = 0; i < 256; i++) s += xq[i] * w[i];
    part[tid] = s;
    __syncthreads();
    if (tid < 64)
        logit[tid] = part[tid] + part[tid + 64] + part[tid + 128] + part[tid + 192];
    __syncthreads();
    if (tid == 0) {
        float lv[NTOPK]; int li[NTOPK];
        for (int k = 0; k < NTOPK; k++) {
            float best = -1e30f; int bi = 0;
            for (int i = 0; i < EDIM; i++) { float v = logit[i]; if (v > best) { best = v; bi = i; } }
            lv[k] = best; li[k] = bi; logit[bi] = -1e30f;
        }
        float m = lv[0], sum = 0.f, wv[NTOPK];
        for (int k = 0; k < NTOPK; k++) { wv[k] = __expf(lv[k] - m); sum += wv[k]; }
        float inv = 1.f / sum;
        for (int k = 0; k < NTOPK; k++) {
            g_topk_idx[t * NTOPK + k] = li[k];
            g_topk_w[t * NTOPK + k]   = wv[k] * inv;
            atomicAdd(&g_count[li[k]], 1);
        }
    }
}

__global__ void prefix_kernel() {
    if (threadIdx.x == 0) {
        int acc = 0;
        for (int e = 0; e < EDIM; e++) { g_offset[e] = acc; acc += g_count[e]; g_fill[e] = 0; }
        g_offset[EDIM] = acc;
    }
}

__global__ void fill_kernel() {
    int i = blockIdx.x * blockDim.x + threadIdx.x;
    if (i >= NSLOTS) return;
    int e = g_topk_idx[i];
    int slot = atomicAdd(&g_fill[e], 1);
    int pos = g_offset[e] + slot;
    g_tok[pos] = i / NTOPK;
    g_tw[pos]  = g_topk_w[i];
}

// ---------------- shared device pieces ----------------
// convert 32 fp32 -> hi/lo bf16 into A smem (one thread = one row half)
__device__ __forceinline__ void a_convert_store(char* sm, const float* xp,
                                                u32 a_elem0) {
#pragma unroll
    for (int j = 0; j < 8; j++) {
        float4 v = *(const float4*)(xp + j * 4);
        __nv_bfloat162 h01 = __floats2bfloat162_rn(v.x, v.y);
        __nv_bfloat162 h23 = __floats2bfloat162_rn(v.z, v.w);
        float lx = v.x - __bfloat162float(__low2bfloat16(h01));
        float ly = v.y - __bfloat162float(__high2bfloat16(h01));
        float lz = v.z - __bfloat162float(__low2bfloat16(h23));
        float lw = v.w - __bfloat162float(__high2bfloat16(h23));
        __nv_bfloat162 l01 = __floats2bfloat162_rn(lx, ly);
        __nv_bfloat162 l23 = __floats2bfloat162_rn(lz, lw);
        u32 off = (a_elem0 + j * 4) * 2;
        *(uint2*)(sm + OFF_AH + off) = make_uint2(*(u32*)&h01, *(u32*)&h23);
        *(uint2*)(sm + OFF_AL + off) = make_uint2(*(u32*)&l01, *(u32*)&l23);
    }
}

// dequant one packed int32 pair -> 8 bf16 (q - z), store contiguous 16B
__device__ __forceinline__ void b_dequant_store(char* sm, int krow, int wc,
                                                unsigned qv, unsigned zv) {
    const int sh[8] = {0, 16, 4, 20, 8, 24, 12, 28};
    u32 packed[4];
#pragma unroll
    for (int j = 0; j < 4; j++) {
        int d0 = (int)((qv >> sh[2 * j])     & 0xF) - (int)((zv >> sh[2 * j])     & 0xF);
        int d1 = (int)((qv >> sh[2 * j + 1]) & 0xF) - (int)((zv >> sh[2 * j + 1]) & 0xF);
        __nv_bfloat162 p = __floats2bfloat162_rn((float)d0, (float)d1);
        packed[j] = *(u32*)&p;
    }
    *(uint4*)(sm + OFF_B + (u32)(krow * BST + wc * 8) * 2) =
        make_uint4(packed[0], packed[1], packed[2], packed[3]);
}

// one KC=64 chunk of warp-level MMA: accg += Ahi*B + Alo*B
__device__ __forceinline__ void warp_mma_chunk(u32 smb, int warp_m, int warp_n,
                                               int lane, float accg[2][4][4]) {
#pragma unroll
    for (int ks = 0; ks < 4; ks++) {
        const int k0 = ks * 16;
        // B frags: 2 x ldmatrix.x4.trans covering n = warp_n*32 .. +31
        u32 b[4][2];
#pragma unroll
        for (int h = 0; h < 2; h++) {
            int tile = lane >> 3, row = lane & 7;
            int kk = k0 + (tile & 1) * 8 + row;
            int nn = warp_n * 32 + h * 16 + (tile >> 1) * 8;
            u32 addr = smb + OFF_B + (u32)(kk * BST + nn) * 2;
            LDMX4T(b[h * 2][0], b[h * 2][1], b[h * 2 + 1][0], b[h * 2 + 1][1], addr);
        }
        // A frags (hi then lo), 2 m-frags each
#pragma unroll
        for (int p = 0; p < 2; p++) {
            const u32 abase = (p == 0) ? (smb + OFF_AH) : (smb + OFF_AL);
#pragma unroll
            for (int mf = 0; mf < 2; mf++) {
                int mm = warp_m * 32 + mf * 16 + (lane & 15);
                int kk = k0 + (lane >> 4) * 8;
                u32 addr = abase + (u32)(mm * AST + kk) * 2;
                u32 a0, a1, a2, a3;
                LDMX4(a0, a1, a2, a3, addr);
                MMA16816(accg[mf][0], a0, a1, a2, a3, b[0][0], b[0][1]);
                MMA16816(accg[mf][1], a0, a1, a2, a3, b[1][0], b[1][1]);
                MMA16816(accg[mf][2], a0, a1, a2, a3, b[2][0], b[2][1]);
                MMA16816(accg[mf][3], a0, a1, a2, a3, b[3][0], b[3][1]);
            }
        }
    }
}

__device__ __forceinline__ void fold_group(float accg[2][4][4], float accf[2][4][4],
                                           const float* sc_g, int warp_n, int lane) {
#pragma unroll
    for (int nf = 0; nf < 4; nf++) {
        int col = warp_n * 32 + nf * 8 + (lane & 3) * 2;
        float s0 = sc_g[col], s1 = sc_g[col + 1];
#pragma unroll
        for (int mf = 0; mf < 2; mf++) {
            accf[mf][nf][0] += s0 * accg[mf][nf][0];
            accf[mf][nf][1] += s1 * accg[mf][nf][1];
            accf[mf][nf][2] += s0 * accg[mf][nf][2];
            accf[mf][nf][3] += s1 * accg[mf][nf][3];
            accg[mf][nf][0] = 0.f; accg[mf][nf][1] = 0.f;
            accg[mf][nf][2] = 0.f; accg[mf][nf][3] = 0.f;
        }
    }
}

// ---------------- GEMM1: g_h = silu(gather(x) @ deqW1^T) * tw ----------------
__global__ __launch_bounds__(256, 2) void gemm1_kernel(const float* __restrict__ x,
                                                       const int*   __restrict__ qw1,
                                                       const int*   __restrict__ qz1,
                                                       const float* __restrict__ sc1) {
    const int e    = blockIdx.z;
    const int base = g_offset[e];
    const int cnt  = g_offset[e + 1] - base;
    const int m0   = blockIdx.y * BM;
    if (m0 >= cnt) return;
    const int i0 = blockIdx.x * BN;

    extern __shared__ char sm[];
    const u32 smb = smem_u32(sm);
    int*   toks_sm = (int*)(sm + OFF_TOKS);
    float* tws_sm  = (float*)(sm + OFF_TWS);
    float* sc_sm   = (float*)(sm + OFF_SC);

    const int tid  = threadIdx.x;
    const int wid  = tid >> 5;
    const int lane = tid & 31;
    const int warp_m = wid & 3;
    const int warp_n = wid >> 2;

    if (tid < 128) {
        toks_sm[tid] = g_tok[base + m0 + tid];
        tws_sm[tid]  = g_tw[base + m0 + tid];
    }
#pragma unroll
    for (int it = 0; it < 2; it++) {
        int idx = it * 256 + tid;
        sc_sm[idx] = sc1[(idx >> 6) * 32768 + e * IDIM + i0 + (idx & 63)];
    }
    __syncthreads();

    const int r    = tid & 127;
    const int half = tid >> 7;
    const float* xrow = x + (size_t)toks_sm[r] * HDIM + half * 32;
    const u32 a_elem0 = (u32)(r * AST + half * 32);

    const int qcolbase = (e * IDIM + i0) >> 3;
    const int krow = tid >> 3;          // 0..31 (x2 iters -> 0..63)
    const int wc   = tid & 7;

    float accg[2][4][4], accf[2][4][4];
#pragma unroll
    for (int a = 0; a < 2; a++)
#pragma unroll
        for (int b = 0; b < 4; b++)
#pragma unroll
            for (int c = 0; c < 4; c++) { accg[a][b][c] = 0.f; accf[a][b][c] = 0.f; }

    const int NCH = HDIM / KC;  // 16
#pragma unroll 1
    for (int c = 0; c < NCH; c++) {
        const int k0 = c * KC;
        if (c > 0) __syncthreads();
        a_convert_store(sm, xrow + k0, a_elem0);
#pragma unroll
        for (int it = 0; it < 2; it++) {
            int kr = it * 32 + krow;
            int kg = k0 + kr;
            unsigned qv = (unsigned)qw1[kg * 4096 + qcolbase + wc];
            unsigned zv = (unsigned)qz1[(kg >> 7) * 4096 + qcolbase + wc];
            b_dequant_store(sm, kr, wc, qv, zv);
        }
        __syncthreads();
        warp_mma_chunk(smb, warp_m, warp_n, lane, accg);
        if (c & 1) fold_group(accg, accf, sc_sm + (c >> 1) * 64, warp_n, lane);
    }

    // epilogue: silu * tw -> g_h
#pragma unroll
    for (int mf = 0; mf < 2; mf++) {
#pragma unroll
        for (int dd = 0; dd < 2; dd++) {   // dd=0 -> d0/d1 (row), dd=1 -> d2/d3 (row+8)
            int ml = warp_m * 32 + mf * 16 + (lane >> 2) + dd * 8;
            int gm = m0 + ml;
            if (gm < cnt) {
                float tw = tws_sm[ml];
                float* op = g_h + (size_t)(base + gm) * IDIM + i0;
#pragma unroll
                for (int nf = 0; nf < 4; nf++) {
                    int col = warp_n * 32 + nf * 8 + (lane & 3) * 2;
                    float2 o = make_float2(silu_f(accf[mf][nf][dd * 2]) * tw,
                                           silu_f(accf[mf][nf][dd * 2 + 1]) * tw);
                    *(float2*)(op + col) = o;
                }
            }
        }
    }
}

// ---------------- GEMM2: out += g_h @ deqW2^T (atomic scatter) ---------------
__global__ __launch_bounds__(256, 2) void gemm2_kernel(const int*   __restrict__ qw2,
                                                       const int*   __restrict__ qz2,
                                                       const float* __restrict__ sc2,
                                                       float* __restrict__ out) {
    const int e    = blockIdx.z;
    const int base = g_offset[e];
    const int cnt  = g_offset[e + 1] - base;
    const int m0   = blockIdx.y * BM;
    if (m0 >= cnt) return;
    const int h0 = blockIdx.x * BN;

    extern __shared__ char sm[];
    const u32 smb = smem_u32(sm);
    int*   toks_sm = (int*)(sm + OFF_TOKS);
    float* sc_sm   = (float*)(sm + OFF_SC);

    const int tid  = threadIdx.x;
    const int wid  = tid >> 5;
    const int lane = tid & 31;
    const int warp_m = wid & 3;
    const int warp_n = wid >> 2;

    if (tid < 128) toks_sm[tid] = g_tok[base + m0 + tid];
    {
        int idx = tid;  // 4 groups x 64 = 256
        sc_sm[idx] = sc2[(idx >> 6) * 65536 + e * HDIM + h0 + (idx & 63)];
    }
    __syncthreads();

    const int r    = tid & 127;
    const int half = tid >> 7;
    const float* xrow = g_h + (size_t)(base + m0 + r) * IDIM + half * 32;
    const u32 a_elem0 = (u32)(r * AST + half * 32);

    const int qcolbase = (e * HDIM + h0) >> 3;
    const int krow = tid >> 3;
    const int wc   = tid & 7;

    float accg[2][4][4], accf[2][4][4];
#pragma unroll
    for (int a = 0; a < 2; a++)
#pragma unroll
        for (int b = 0; b < 4; b++)
#pragma unroll
            for (int c = 0; c < 4; c++) { accg[a][b][c] = 0.f; accf[a][b][c] = 0.f; }

    const int NCH = IDIM / KC;  // 8
#pragma unroll 1
    for (int c = 0; c < NCH; c++) {
        const int k0 = c * KC;
        if (c > 0) __syncthreads();
        a_convert_store(sm, xrow + k0, a_elem0);
#pragma unroll
        for (int it = 0; it < 2; it++) {
            int kr = it * 32 + krow;
            int kg = k0 + kr;
            unsigned qv = (unsigned)qw2[kg * 8192 + qcolbase + wc];
            unsigned zv = (unsigned)qz2[(kg >> 7) * 8192 + qcolbase + wc];
            b_dequant_store(sm, kr, wc, qv, zv);
        }
        __syncthreads();
        warp_mma_chunk(smb, warp_m, warp_n, lane, accg);
        if (c & 1) fold_group(accg, accf, sc_sm + (c >> 1) * 64, warp_n, lane);
    }

#pragma unroll
    for (int mf = 0; mf < 2; mf++) {
#pragma unroll
        for (int dd = 0; dd < 2; dd++) {
            int ml = warp_m * 32 + mf * 16 + (lane >> 2) + dd * 8;
            int gm = m0 + ml;
            if (gm < cnt) {
                float* op = out + (size_t)toks_sm[ml] * HDIM + h0;
#pragma unroll
                for (int nf = 0; nf < 4; nf++) {
                    int col = warp_n * 32 + nf * 8 + (lane & 3) * 2;
                    atomicAdd(op + col,     accf[mf][nf][dd * 2]);
                    atomicAdd(op + col + 1, accf[mf][nf][dd * 2 + 1]);
                }
            }
        }
    }
}

// ---------------- launch ----------------
extern "C" void kernel_launch(void* const* d_in, const int* in_sizes, int n_in,
                              void* d_out, int out_size) {
    const float* x   = (const float*)d_in[0];
    const float* gw  = (const float*)d_in[1];
    const int*   qw1 = (const int*)d_in[2];
    const int*   qz1 = (const int*)d_in[3];
    const float* sc1 = (const float*)d_in[4];
    const int*   qw2 = (const int*)d_in[5];
    const int*   qz2 = (const int*)d_in[6];
    const float* sc2 = (const float*)d_in[7];
    float* out = (float*)d_out;

    cudaFuncSetAttribute(gemm1_kernel, cudaFuncAttributeMaxDynamicSharedMemorySize, SMEM_TOTAL);
    cudaFuncSetAttribute(gemm2_kernel, cudaFuncAttributeMaxDynamicSharedMemorySize, SMEM_TOTAL);

    init_kernel<<<1, 64>>>();
    route_kernel<<<T_TOK, 256>>>(x, gw);
    prefix_kernel<<<1, 1>>>();
    fill_kernel<<<(NSLOTS + 255) / 256, 256>>>();
    cudaMemsetAsync(out, 0, (size_t)out_size * sizeof(float), 0);
    gemm1_kernel<<<dim3(IDIM / BN, T_TOK / BM, EDIM), 256, SMEM_TOTAL>>>(x, qw1, qz1, sc1);
    gemm2_kernel<<<dim3(HDIM / BN, T_TOK / BM, EDIM), 256, SMEM_TOTAL>>>(qw2, qz2, sc2, out);
}

// round 7
// speedup vs baseline: 4.8224x; 1.3144x over previous
#include <cuda_runtime.h>
#include <cuda_bf16.h>
#include <cstdint>
#include <cstddef>

#define T_TOK 2048
#define HDIM  1024
#define EDIM  64
#define NTOPK 8
#define IDIM  512

#define NSLOTS (T_TOK * NTOPK)      // 16384
#define PADSLOTS (NSLOTS + 128)

#define BM 128
#define BN 64
#define KC 64

// per-stage smem layout (bytes)
#define STG_A_HI 0                   // 128 x 64 bf16 = 16384
#define STG_A_LO 16384
#define STG_B    32768               // 64 x 64 bf16 = 8192
#define STG_SIZE 40960
#define OFF_TOKS 81920               // 128 ints
#define OFF_TWS  82432               // 128 floats
#define OFF_SC   82944               // 512 floats
#define SMEM_TOTAL 84992

typedef unsigned int u32;

// ---------------- device scratch ----------------
__device__ int   g_count[EDIM];
__device__ int   g_offset[EDIM + 1];
__device__ int   g_fill[EDIM];
__device__ int   g_topk_idx[NSLOTS];
__device__ float g_topk_w[NSLOTS];
__device__ int   g_tok[PADSLOTS];
__device__ float g_tw[PADSLOTS];
__device__ __nv_bfloat16 g_xhi[(size_t)T_TOK * HDIM];
__device__ __nv_bfloat16 g_xlo[(size_t)T_TOK * HDIM];
__device__ __nv_bfloat16 g_hh[(size_t)PADSLOTS * IDIM];
__device__ __nv_bfloat16 g_hl[(size_t)PADSLOTS * IDIM];
__device__ __nv_bfloat16 g_w1deq[(size_t)HDIM * (EDIM * IDIM)];   // 64 MB
__device__ __nv_bfloat16 g_w2deq[(size_t)IDIM * (EDIM * HDIM)];   // 64 MB

__device__ __forceinline__ float silu_f(float v) { return v / (1.0f + __expf(-v)); }

__device__ __forceinline__ u32 smem_u32(const void* p) {
    u32 a;
    asm("{ .reg .u64 t; cvta.to.shared.u64 t, %1; cvt.u32.u64 %0, t; }" : "=r"(a) : "l"(p));
    return a;
}

__device__ __forceinline__ void cp_async16(u32 dst, const void* src) {
    asm volatile("cp.async.cg.shared.global [%0], [%1], 16;" :: "r"(dst), "l"(src));
}
#define CP_COMMIT() asm volatile("cp.async.commit_group;" ::: "memory")
#define CP_WAIT(n)  asm volatile("cp.async.wait_group %0;" :: "n"(n) : "memory")

#define LDMX4(r0, r1, r2, r3, addr) \
    asm volatile("ldmatrix.sync.aligned.m8n8.x4.shared.b16 {%0,%1,%2,%3}, [%4];" \
                 : "=r"(r0), "=r"(r1), "=r"(r2), "=r"(r3) : "r"(addr))

#define LDMX4T(r0, r1, r2, r3, addr) \
    asm volatile("ldmatrix.sync.aligned.m8n8.x4.trans.shared.b16 {%0,%1,%2,%3}, [%4];" \
                 : "=r"(r0), "=r"(r1), "=r"(r2), "=r"(r3) : "r"(addr))

#define MMA16816(d, a0, a1, a2, a3, b0, b1) \
    asm volatile("mma.sync.aligned.m16n8k16.row.col.f32.bf16.bf16.f32 " \
                 "{%0,%1,%2,%3}, {%4,%5,%6,%7}, {%8,%9}, {%0,%1,%2,%3};" \
                 : "+f"((d)[0]), "+f"((d)[1]), "+f"((d)[2]), "+f"((d)[3]) \
                 : "r"(a0), "r"(a1), "r"(a2), "r"(a3), "r"(b0), "r"(b1))

// ---------------- pre-processing kernels ----------------
// AWQ (q - z) -> exact bf16 dense weights [K][N].
// NOTE: destination selected in DEVICE code (cannot pass __device__ symbol from host).
__global__ __launch_bounds__(256) void dequant_kernel(const int* __restrict__ qw,
                                                      const int* __restrict__ qz,
                                                      int ncol8, int which) {
    __nv_bfloat16* __restrict__ wdeq = which ? g_w2deq : g_w1deq;
    int idx = blockIdx.x * 256 + threadIdx.x;
    int k = idx / ncol8, c8 = idx - k * ncol8;
    unsigned qv = (unsigned)qw[idx];
    unsigned zv = (unsigned)qz[(k >> 7) * ncol8 + c8];
    const int sh[8] = {0, 16, 4, 20, 8, 24, 12, 28};
    u32 o[4];
#pragma unroll
    for (int j = 0; j < 4; j++) {
        int d0 = (int)((qv >> sh[2 * j])     & 0xF) - (int)((zv >> sh[2 * j])     & 0xF);
        int d1 = (int)((qv >> sh[2 * j + 1]) & 0xF) - (int)((zv >> sh[2 * j + 1]) & 0xF);
        __nv_bfloat162 p = __floats2bfloat162_rn((float)d0, (float)d1);
        o[j] = *(u32*)&p;
    }
    *(uint4*)(wdeq + (size_t)idx * 8) = make_uint4(o[0], o[1], o[2], o[3]);
}

// x fp32 -> hi/lo bf16 split
__global__ __launch_bounds__(256) void xsplit_kernel(const float* __restrict__ x) {
    int i = blockIdx.x * 256 + threadIdx.x;     // one float4
    float4 v = *(const float4*)(x + (size_t)i * 4);
    __nv_bfloat162 h01 = __floats2bfloat162_rn(v.x, v.y);
    __nv_bfloat162 h23 = __floats2bfloat162_rn(v.z, v.w);
    float lx = v.x - __bfloat162float(__low2bfloat16(h01));
    float ly = v.y - __bfloat162float(__high2bfloat16(h01));
    float lz = v.z - __bfloat162float(__low2bfloat16(h23));
    float lw = v.w - __bfloat162float(__high2bfloat16(h23));
    __nv_bfloat162 l01 = __floats2bfloat162_rn(lx, ly);
    __nv_bfloat162 l23 = __floats2bfloat162_rn(lz, lw);
    *(uint2*)(g_xhi + (size_t)i * 4) = make_uint2(*(u32*)&h01, *(u32*)&h23);
    *(uint2*)(g_xlo + (size_t)i * 4) = make_uint2(*(u32*)&l01, *(u32*)&l23);
}

// ---------------- routing kernels ----------------
__global__ void init_kernel() {
    int i = threadIdx.x;
    if (i < EDIM) g_count[i] = 0;
}

__global__ __launch_bounds__(256) void route_kernel(const float* __restrict__ x,
                                                    const float* __restrict__ gw) {
    int t = blockIdx.x;
    __shared__ float xs[HDIM];
    __shared__ float part[256];
    __shared__ float logit[EDIM];
    int tid = threadIdx.x;
    for (int i = tid; i < HDIM; i += 256) xs[i] = x[t * HDIM + i];
    __syncthreads();
    int e = tid & 63, q = tid >> 6;
    const float* w  = gw + e * HDIM + q * 256;
    const float* xq = xs + q * 256;
    float s = 0.f;
#pragma unroll 8
    for (int i = 0; i < 256; i++) s += xq[i] * w[i];
    part[tid] = s;
    __syncthreads();
    if (tid < 64)
        logit[tid] = part[tid] + part[tid + 64] + part[tid + 128] + part[tid + 192];
    __syncthreads();
    if (tid == 0) {
        float lv[NTOPK]; int li[NTOPK];
        for (int k = 0; k < NTOPK; k++) {
            float best = -1e30f; int bi = 0;
            for (int i = 0; i < EDIM; i++) { float v = logit[i]; if (v > best) { best = v; bi = i; } }
            lv[k] = best; li[k] = bi; logit[bi] = -1e30f;
        }
        float m = lv[0], sum = 0.f, wv[NTOPK];
        for (int k = 0; k < NTOPK; k++) { wv[k] = __expf(lv[k] - m); sum += wv[k]; }
        float inv = 1.f / sum;
        for (int k = 0; k < NTOPK; k++) {
            g_topk_idx[t * NTOPK + k] = li[k];
            g_topk_w[t * NTOPK + k]   = wv[k] * inv;
            atomicAdd(&g_count[li[k]], 1);
        }
    }
}

__global__ void prefix_kernel() {
    if (threadIdx.x == 0) {
        int acc = 0;
        for (int e = 0; e < EDIM; e++) { g_offset[e] = acc; acc += g_count[e]; g_fill[e] = 0; }
        g_offset[EDIM] = acc;
    }
}

__global__ void fill_kernel() {
    int i = blockIdx.x * blockDim.x + threadIdx.x;
    if (i >= NSLOTS) return;
    int e = g_topk_idx[i];
    int slot = atomicAdd(&g_fill[e], 1);
    int pos = g_offset[e] + slot;
    g_tok[pos] = i / NTOPK;
    g_tw[pos]  = g_topk_w[i];
}

// ---------------- warp MMA over one KC=64 stage ----------------
__device__ __forceinline__ void warp_mma_chunk(u32 sb, int warp_m, int warp_n,
                                               int lane, float accg[2][4][4]) {
#pragma unroll
    for (int ks = 0; ks < 4; ks++) {
        u32 b[4][2];
#pragma unroll
        for (int h = 0; h < 2; h++) {
            int tile = lane >> 3, row = lane & 7;
            int kk = ks * 16 + (tile & 1) * 8 + row;
            int nn = warp_n * 32 + h * 16 + (tile >> 1) * 8;
            int ch = nn >> 3;
            u32 addr = sb + STG_B + (u32)(kk * 128 + ((ch ^ (kk & 7)) << 4));
            LDMX4T(b[h * 2][0], b[h * 2][1], b[h * 2 + 1][0], b[h * 2 + 1][1], addr);
        }
#pragma unroll
        for (int p = 0; p < 2; p++) {
            const u32 abase = sb + (p ? STG_A_LO : STG_A_HI);
#pragma unroll
            for (int mf = 0; mf < 2; mf++) {
                int mm = warp_m * 32 + mf * 16 + (lane & 15);
                int ch = ks * 2 + (lane >> 4);
                u32 addr = abase + (u32)(mm * 128 + ((ch ^ (mm & 7)) << 4));
                u32 a0, a1, a2, a3;
                LDMX4(a0, a1, a2, a3, addr);
                MMA16816(accg[mf][0], a0, a1, a2, a3, b[0][0], b[0][1]);
                MMA16816(accg[mf][1], a0, a1, a2, a3, b[1][0], b[1][1]);
                MMA16816(accg[mf][2], a0, a1, a2, a3, b[2][0], b[2][1]);
                MMA16816(accg[mf][3], a0, a1, a2, a3, b[3][0], b[3][1]);
            }
        }
    }
}

__device__ __forceinline__ void fold_group(float accg[2][4][4], float accf[2][4][4],
                                           const float* sc_g, int warp_n, int lane) {
#pragma unroll
    for (int nf = 0; nf < 4; nf++) {
        int col = warp_n * 32 + nf * 8 + (lane & 3) * 2;
        float s0 = sc_g[col], s1 = sc_g[col + 1];
#pragma unroll
        for (int mf = 0; mf < 2; mf++) {
            accf[mf][nf][0] += s0 * accg[mf][nf][0];
            accf[mf][nf][1] += s1 * accg[mf][nf][1];
            accf[mf][nf][2] += s0 * accg[mf][nf][2];
            accf[mf][nf][3] += s1 * accg[mf][nf][3];
            accg[mf][nf][0] = 0.f; accg[mf][nf][1] = 0.f;
            accg[mf][nf][2] = 0.f; accg[mf][nf][3] = 0.f;
        }
    }
}

// ---------------- GEMM1 ----------------
__global__ __launch_bounds__(256) void gemm1_kernel(const float* __restrict__ sc1) {
    const int e    = blockIdx.z;
    const int base = g_offset[e];
    const int cnt  = g_offset[e + 1] - base;
    const int m0   = blockIdx.y * BM;
    if (m0 >= cnt) return;
    const int i0 = blockIdx.x * BN;

    extern __shared__ char sm[];
    const u32 smb = smem_u32(sm);
    int*   toks_sm = (int*)(sm + OFF_TOKS);
    float* tws_sm  = (float*)(sm + OFF_TWS);
    float* sc_sm   = (float*)(sm + OFF_SC);

    const int tid  = threadIdx.x;
    const int wid  = tid >> 5;
    const int lane = tid & 31;
    const int warp_m = wid & 3;
    const int warp_n = wid >> 2;

    if (tid < 128) {
        toks_sm[tid] = g_tok[base + m0 + tid];
        tws_sm[tid]  = g_tw[base + m0 + tid];
    }
#pragma unroll
    for (int it = 0; it < 2; it++) {
        int idx = it * 256 + tid;
        sc_sm[idx] = sc1[(idx >> 6) * 32768 + e * IDIM + i0 + (idx & 63)];
    }
    __syncthreads();

    // loader setup
    const __nv_bfloat16* a_hi[4];
    const __nv_bfloat16* a_lo[4];
    u32 a_dst[4];
#pragma unroll
    for (int it = 0; it < 4; it++) {
        int idx = it * 256 + tid;
        int m = idx >> 3, cc = idx & 7;
        size_t rb = (size_t)toks_sm[m] * HDIM + cc * 8;
        a_hi[it] = g_xhi + rb;
        a_lo[it] = g_xlo + rb;
        a_dst[it] = (u32)(m * 128 + ((cc ^ (m & 7)) << 4));
    }
    u32 b_dst[2]; size_t b_src[2];
    const int ncolbase = e * IDIM + i0;
#pragma unroll
    for (int it = 0; it < 2; it++) {
        int idx = it * 256 + tid;
        int kr = idx >> 3, cc = idx & 7;
        b_dst[it] = (u32)(STG_B + kr * 128 + ((cc ^ (kr & 7)) << 4));
        b_src[it] = (size_t)kr * 32768 + ncolbase + cc * 8;
    }

    auto load_stage = [&](int c) {
        u32 sb = smb + (c & 1) * STG_SIZE;
        const int k0 = c * KC;
#pragma unroll
        for (int it = 0; it < 4; it++) {
            cp_async16(sb + STG_A_HI + a_dst[it], a_hi[it] + k0);
            cp_async16(sb + STG_A_LO + a_dst[it], a_lo[it] + k0);
        }
        const __nv_bfloat16* wb = g_w1deq + (size_t)k0 * 32768;
#pragma unroll
        for (int it = 0; it < 2; it++)
            cp_async16(sb + b_dst[it], wb + b_src[it]);
    };

    float accg[2][4][4], accf[2][4][4];
#pragma unroll
    for (int a = 0; a < 2; a++)
#pragma unroll
        for (int b = 0; b < 4; b++)
#pragma unroll
            for (int c = 0; c < 4; c++) { accg[a][b][c] = 0.f; accf[a][b][c] = 0.f; }

    const int NCH = HDIM / KC;  // 16
    load_stage(0); CP_COMMIT();
#pragma unroll 1
    for (int c = 0; c < NCH; c++) {
        if (c + 1 < NCH) { load_stage(c + 1); CP_COMMIT(); CP_WAIT(1); }
        else             { CP_WAIT(0); }
        __syncthreads();
        warp_mma_chunk(smb + (c & 1) * STG_SIZE, warp_m, warp_n, lane, accg);
        if (c & 1) fold_group(accg, accf, sc_sm + (c >> 1) * 64, warp_n, lane);
        __syncthreads();
    }

    // epilogue: silu * tw -> bf16 hi/lo pair
#pragma unroll
    for (int mf = 0; mf < 2; mf++) {
#pragma unroll
        for (int dd = 0; dd < 2; dd++) {
            int ml = warp_m * 32 + mf * 16 + (lane >> 2) + dd * 8;
            int gm = m0 + ml;
            if (gm < cnt) {
                float tw = tws_sm[ml];
                __nv_bfloat16* oph = g_hh + (size_t)(base + gm) * IDIM + i0;
                __nv_bfloat16* opl = g_hl + (size_t)(base + gm) * IDIM + i0;
#pragma unroll
                for (int nf = 0; nf < 4; nf++) {
                    int col = warp_n * 32 + nf * 8 + (lane & 3) * 2;
                    float v0 = silu_f(accf[mf][nf][dd * 2]) * tw;
                    float v1 = silu_f(accf[mf][nf][dd * 2 + 1]) * tw;
                    __nv_bfloat162 h = __floats2bfloat162_rn(v0, v1);
                    float l0 = v0 - __bfloat162float(__low2bfloat16(h));
                    float l1 = v1 - __bfloat162float(__high2bfloat16(h));
                    __nv_bfloat162 l = __floats2bfloat162_rn(l0, l1);
                    *(u32*)(oph + col) = *(u32*)&h;
                    *(u32*)(opl + col) = *(u32*)&l;
                }
            }
        }
    }
}

// ---------------- GEMM2 ----------------
__global__ __launch_bounds__(256) void gemm2_kernel(const float* __restrict__ sc2,
                                                    float* __restrict__ out) {
    const int e    = blockIdx.z;
    const int base = g_offset[e];
    const int cnt  = g_offset[e + 1] - base;
    const int m0   = blockIdx.y * BM;
    if (m0 >= cnt) return;
    const int h0 = blockIdx.x * BN;

    extern __shared__ char sm[];
    const u32 smb = smem_u32(sm);
    int*   toks_sm = (int*)(sm + OFF_TOKS);
    float* sc_sm   = (float*)(sm + OFF_SC);

    const int tid  = threadIdx.x;
    const int wid  = tid >> 5;
    const int lane = tid & 31;
    const int warp_m = wid & 3;
    const int warp_n = wid >> 2;

    if (tid < 128) toks_sm[tid] = g_tok[base + m0 + tid];
    sc_sm[tid] = sc2[(tid >> 6) * 65536 + e * HDIM + h0 + (tid & 63)];
    __syncthreads();

    const __nv_bfloat16* a_hi[4];
    const __nv_bfloat16* a_lo[4];
    u32 a_dst[4];
#pragma unroll
    for (int it = 0; it < 4; it++) {
        int idx = it * 256 + tid;
        int m = idx >> 3, cc = idx & 7;
        size_t rb = (size_t)(base + m0 + m) * IDIM + cc * 8;
        a_hi[it] = g_hh + rb;
        a_lo[it] = g_hl + rb;
        a_dst[it] = (u32)(m * 128 + ((cc ^ (m & 7)) << 4));
    }
    u32 b_dst[2]; size_t b_src[2];
    const int ncolbase = e * HDIM + h0;
#pragma unroll
    for (int it = 0; it < 2; it++) {
        int idx = it * 256 + tid;
        int kr = idx >> 3, cc = idx & 7;
        b_dst[it] = (u32)(STG_B + kr * 128 + ((cc ^ (kr & 7)) << 4));
        b_src[it] = (size_t)kr * 65536 + ncolbase + cc * 8;
    }

    auto load_stage = [&](int c) {
        u32 sb = smb + (c & 1) * STG_SIZE;
        const int k0 = c * KC;
#pragma unroll
        for (int it = 0; it < 4; it++) {
            cp_async16(sb + STG_A_HI + a_dst[it], a_hi[it] + k0);
            cp_async16(sb + STG_A_LO + a_dst[it], a_lo[it] + k0);
        }
        const __nv_bfloat16* wb = g_w2deq + (size_t)k0 * 65536;
#pragma unroll
        for (int it = 0; it < 2; it++)
            cp_async16(sb + b_dst[it], wb + b_src[it]);
    };

    float accg[2][4][4], accf[2][4][4];
#pragma unroll
    for (int a = 0; a < 2; a++)
#pragma unroll
        for (int b = 0; b < 4; b++)
#pragma unroll
            for (int c = 0; c < 4; c++) { accg[a][b][c] = 0.f; accf[a][b][c] = 0.f; }

    const int NCH = IDIM / KC;  // 8
    load_stage(0); CP_COMMIT();
#pragma unroll 1
    for (int c = 0; c < NCH; c++) {
        if (c + 1 < NCH) { load_stage(c + 1); CP_COMMIT(); CP_WAIT(1); }
        else             { CP_WAIT(0); }
        __syncthreads();
        warp_mma_chunk(smb + (c & 1) * STG_SIZE, warp_m, warp_n, lane, accg);
        if (c & 1) fold_group(accg, accf, sc_sm + (c >> 1) * 64, warp_n, lane);
        __syncthreads();
    }

#pragma unroll
    for (int mf = 0; mf < 2; mf++) {
#pragma unroll
        for (int dd = 0; dd < 2; dd++) {
            int ml = warp_m * 32 + mf * 16 + (lane >> 2) + dd * 8;
            int gm = m0 + ml;
            if (gm < cnt) {
                float* op = out + (size_t)toks_sm[ml] * HDIM + h0;
#pragma unroll
                for (int nf = 0; nf < 4; nf++) {
                    int col = warp_n * 32 + nf * 8 + (lane & 3) * 2;
                    atomicAdd(op + col,     accf[mf][nf][dd * 2]);
                    atomicAdd(op + col + 1, accf[mf][nf][dd * 2 + 1]);
                }
            }
        }
    }
}

// ---------------- launch ----------------
extern "C" void kernel_launch(void* const* d_in, const int* in_sizes, int n_in,
                              void* d_out, int out_size) {
    const float* x   = (const float*)d_in[0];
    const float* gw  = (const float*)d_in[1];
    const int*   qw1 = (const int*)d_in[2];
    const int*   qz1 = (const int*)d_in[3];
    const float* sc1 = (const float*)d_in[4];
    const int*   qw2 = (const int*)d_in[5];
    const int*   qz2 = (const int*)d_in[6];
    const float* sc2 = (const float*)d_in[7];
    float* out = (float*)d_out;

    cudaFuncSetAttribute(gemm1_kernel, cudaFuncAttributeMaxDynamicSharedMemorySize, SMEM_TOTAL);
    cudaFuncSetAttribute(gemm2_kernel, cudaFuncAttributeMaxDynamicSharedMemorySize, SMEM_TOTAL);

    init_kernel<<<1, 64>>>();
    route_kernel<<<T_TOK, 256>>>(x, gw);
    dequant_kernel<<<(HDIM * 4096) / 256, 256>>>(qw1, qz1, 4096, 0);
    dequant_kernel<<<(IDIM * 8192) / 256, 256>>>(qw2, qz2, 8192, 1);
    xsplit_kernel<<<(T_TOK * HDIM / 4) / 256, 256>>>(x);
    prefix_kernel<<<1, 1>>>();
    fill_kernel<<<(NSLOTS + 255) / 256, 256>>>();
    cudaMemsetAsync(out, 0, (size_t)out_size * sizeof(float), 0);
    gemm1_kernel<<<dim3(IDIM / BN, T_TOK / BM, EDIM), 256, SMEM_TOTAL>>>(sc1);
    gemm2_kernel<<<dim3(HDIM / BN, T_TOK / BM, EDIM), 256, SMEM_TOTAL>>>(sc2, out);
}